// round 10
// baseline (speedup 1.0000x reference)
#include <cuda_runtime.h>
#include <math.h>

// CroquetGNN: 2-layer GCN, N=100000, E=3200000, feat 3 -> 16 -> 1
// out = sigmoid( GCNConv2( relu( GCNConv1(x) ) ) )
// GCNConv(x) = dinv[d] * segsum_{s->d}( dinv[s]*x[s] ) @ W (+ self loop + b)
//
// Pull-mode padded CSR (CAP=128; deg~Poisson(32)). Aggregation: 8-lane segments,
// TWO nodes per segment with interleaved independent gathers (high MLP), shfl
// reduce + epilogue amortized over both nodes. No aggregation atomics.

#define MAXN 100000
#define CAP 128          // padded row capacity
#define TB 256
#define SPN 8            // lanes per node segment

// ---- scratch (static device globals, BSS-zeroed at load; no allocation) ----
__device__ int    g_cnt[MAXN];        // degree counter (reset in k_layer2)
__device__ int    g_csr[MAXN * CAP];  // padded adjacency: src lists per dst
__device__ float  g_dinv[MAXN];       // rsqrt(deg+1)
__device__ float4 g_xd[MAXN];         // dinv[i] * x[i] (padded)
__device__ float  g_gd[MAXN];         // dinv[i]*(relu(conv1).W2)

// per-block dtype detect from INPUT only: int64 LE with values < 2^31 has zero hi words
__device__ __forceinline__ int detect64_block(const int* __restrict__ idx) {
    __shared__ int s64;
    if (threadIdx.x < 32) {
        int hi = __ldg(&idx[2 * threadIdx.x + 1]);
        unsigned m = __ballot_sync(0xFFFFFFFFu, hi == 0);
        if (threadIdx.x == 0) s64 = (m == 0xFFFFFFFFu);
    }
    __syncthreads();
    return s64;
}

// ---- k_scatter: one pass — count degree AND build padded CSR ----
__global__ void __launch_bounds__(TB) k_scatter(const int* __restrict__ idx, int E) {
    int is64 = detect64_block(idx);
    int e = blockIdx.x * TB + threadIdx.x;
    if (e >= E) return;
    int s, d;
    if (is64) {
        const long long* __restrict__ p = (const long long*)idx;
        s = (int)__ldg(&p[e]);
        d = (int)__ldg(&p[E + e]);
    } else {
        s = __ldg(&idx[e]);
        d = __ldg(&idx[E + e]);
    }
    int pos = atomicAdd(&g_cnt[d], 1);
    if (pos < CAP) g_csr[d * CAP + pos] = s;   // guard: never corrupt neighbors
}

// ---- k_xd: dinv = rsqrt(deg+1); xd = dinv*x  (cnt kept; layers read it) ----
__global__ void __launch_bounds__(TB) k_xd(const float* __restrict__ x, int N) {
    int i = blockIdx.x * TB + threadIdx.x;
    if (i >= N) return;
    float di = rsqrtf((float)(g_cnt[i] + 1));   // +1 self loop
    g_dinv[i] = di;
    g_xd[i] = make_float4(x[3 * i] * di, x[3 * i + 1] * di, x[3 * i + 2] * di, 0.f);
}

// ---- k_layer1: 8-lane segment, 2 nodes/segment, interleaved gathers -> gd ----
__global__ void __launch_bounds__(TB) k_layer1(const float* __restrict__ W1,
                                               const float* __restrict__ b1,
                                               const float* __restrict__ W2, int N) {
    __shared__ float sW1[48], sb1[16], sW2[16];
    int t = threadIdx.x;
    if (t < 48) sW1[t] = __ldg(&W1[t]);
    if (t < 16) { sb1[t] = __ldg(&b1[t]); sW2[t] = __ldg(&W2[t]); }
    __syncthreads();

    int lane8 = t & (SPN - 1);
    int seg = (blockIdx.x * TB + t) / SPN;
    int n0 = 2 * seg, n1 = 2 * seg + 1;
    bool v0n = (n0 < N), v1n = (n1 < N);
    int nd0 = v0n ? n0 : 0, nd1 = v1n ? n1 : 0;

    int deg0 = v0n ? min(g_cnt[nd0], CAP) : 0;
    int deg1 = v1n ? min(g_cnt[nd1], CAP) : 0;
    const int* __restrict__ row0 = &g_csr[nd0 * CAP];
    const int* __restrict__ row1 = &g_csr[nd1 * CAP];
    int degmax = max(deg0, deg1);

    float a0 = 0.f, a1 = 0.f, a2 = 0.f;   // node0 accum
    float c0 = 0.f, c1 = 0.f, c2 = 0.f;   // node1 accum
#pragma unroll 4
    for (int j = lane8; j < degmax; j += SPN) {
        if (j < deg0) {
            float4 v = g_xd[row0[j]];
            a0 += v.x; a1 += v.y; a2 += v.z;
        }
        if (j < deg1) {
            float4 v = g_xd[row1[j]];
            c0 += v.x; c1 += v.y; c2 += v.z;
        }
    }
    // 8-lane butterfly reduce (covers both nodes' accumulators)
#pragma unroll
    for (int o = SPN / 2; o; o >>= 1) {
        a0 += __shfl_xor_sync(0xFFFFFFFFu, a0, o);
        a1 += __shfl_xor_sync(0xFFFFFFFFu, a1, o);
        a2 += __shfl_xor_sync(0xFFFFFFFFu, a2, o);
        c0 += __shfl_xor_sync(0xFFFFFFFFu, c0, o);
        c1 += __shfl_xor_sync(0xFFFFFFFFu, c1, o);
        c2 += __shfl_xor_sync(0xFFFFFFFFu, c2, o);
    }
    float di0 = v0n ? g_dinv[nd0] : 0.f;
    float di1 = v1n ? g_dinv[nd1] : 0.f;
    float4 xd0 = g_xd[nd0];
    float4 xd1 = g_xd[nd1];
    // self-loop contributes dinv^2 * x = dinv * xd
    float u0 = di0 * (a0 + xd0.x), u1 = di0 * (a1 + xd0.y), u2 = di0 * (a2 + xd0.z);
    float w0 = di1 * (c0 + xd1.x), w1 = di1 * (c1 + xd1.y), w2 = di1 * (c2 + xd1.z);
    // 16 hidden channels over 8 lanes: 2 per lane, for both nodes
    int ch0 = lane8, ch1 = lane8 + 8;
    float h00 = fmaf(u0, sW1[ch0], fmaf(u1, sW1[16 + ch0], fmaf(u2, sW1[32 + ch0], sb1[ch0])));
    float h01 = fmaf(u0, sW1[ch1], fmaf(u1, sW1[16 + ch1], fmaf(u2, sW1[32 + ch1], sb1[ch1])));
    float h10 = fmaf(w0, sW1[ch0], fmaf(w1, sW1[16 + ch0], fmaf(w2, sW1[32 + ch0], sb1[ch0])));
    float h11 = fmaf(w0, sW1[ch1], fmaf(w1, sW1[16 + ch1], fmaf(w2, sW1[32 + ch1], sb1[ch1])));
    float p = fmaxf(h00, 0.f) * sW2[ch0] + fmaxf(h01, 0.f) * sW2[ch1];
    float q = fmaxf(h10, 0.f) * sW2[ch0] + fmaxf(h11, 0.f) * sW2[ch1];
#pragma unroll
    for (int o = SPN / 2; o; o >>= 1) {
        p += __shfl_xor_sync(0xFFFFFFFFu, p, o);
        q += __shfl_xor_sync(0xFFFFFFFFu, q, o);
    }
    if (lane8 == 0 && v0n) g_gd[nd0] = p * di0;
    if (lane8 == 1 && v1n) g_gd[nd1] = __shfl_sync(0xFFFFFFFFu, q * di1, (t & ~(SPN - 1)) & 31) ,
        g_gd[nd1] = q * di1;   // q is uniform across the segment after butterfly
}

// ---- k_layer2: 8-lane segment, 2 nodes/segment pull of gd + sigmoid; resets cnt ----
__global__ void __launch_bounds__(TB) k_layer2(const float* __restrict__ b2,
                                               float* __restrict__ out, int N) {
    float bias2 = __ldg(&b2[0]);
    int t = threadIdx.x;
    int lane8 = t & (SPN - 1);
    int seg = (blockIdx.x * TB + t) / SPN;
    int n0 = 2 * seg, n1 = 2 * seg + 1;
    bool v0n = (n0 < N), v1n = (n1 < N);
    int nd0 = v0n ? n0 : 0, nd1 = v1n ? n1 : 0;

    int deg0 = v0n ? min(g_cnt[nd0], CAP) : 0;
    int deg1 = v1n ? min(g_cnt[nd1], CAP) : 0;
    const int* __restrict__ row0 = &g_csr[nd0 * CAP];
    const int* __restrict__ row1 = &g_csr[nd1 * CAP];
    int degmax = max(deg0, deg1);

    float a = 0.f, c = 0.f;
#pragma unroll 4
    for (int j = lane8; j < degmax; j += SPN) {
        if (j < deg0) a += g_gd[row0[j]];
        if (j < deg1) c += g_gd[row1[j]];
    }
#pragma unroll
    for (int o = SPN / 2; o; o >>= 1) {
        a += __shfl_xor_sync(0xFFFFFFFFu, a, o);
        c += __shfl_xor_sync(0xFFFFFFFFu, c, o);
    }
    if (lane8 == 0 && v0n) {
        g_cnt[nd0] = 0;               // consumer reset for next replay
        float di = g_dinv[nd0];
        float s = di * (a + g_gd[nd0]) + bias2;
        out[nd0] = 1.0f / (1.0f + expf(-s));
    }
    if (lane8 == 1 && v1n) {
        g_cnt[nd1] = 0;
        float di = g_dinv[nd1];
        float s = di * (c + g_gd[nd1]) + bias2;
        out[nd1] = 1.0f / (1.0f + expf(-s));
    }
}

extern "C" void kernel_launch(void* const* d_in, const int* in_sizes, int n_in,
                              void* d_out, int out_size) {
    const float* x   = (const float*)d_in[0];
    const int*   idx = (const int*)d_in[1];   // int32 or int64 (device-detected)
    const float* W1  = (const float*)d_in[2];
    const float* b1  = (const float*)d_in[3];
    const float* W2  = (const float*)d_in[4];
    const float* b2  = (const float*)d_in[5];
    float* out = (float*)d_out;

    int N_ = in_sizes[0] / 3;   // 100000
    int E_ = in_sizes[1] / 2;   // 3200000

    int nb_e = (E_ + TB - 1) / TB;
    int nb_n = (N_ + TB - 1) / TB;
    int nsegs = (N_ + 1) / 2;                   // 2 nodes per segment
    int nb_s = (nsegs * SPN + TB - 1) / TB;

    k_scatter<<<nb_e, TB>>>(idx, E_);
    k_xd    <<<nb_n, TB>>>(x, N_);
    k_layer1<<<nb_s, TB>>>(W1, b1, W2, N_);
    k_layer2<<<nb_s, TB>>>(b2, out, N_);
}